// round 10
// baseline (speedup 1.0000x reference)
#include <cuda_runtime.h>
#include <cstdint>

// ---------------- problem constants ----------------
#define KI     9
#define KO     3
#define C_IN   3
#define H_IN   192
#define W_IN   192
#define B2     16
#define HP     184            // H - KI + 1
#define OUT_H  186

// ---------------- tiling ----------------
#define TROWS  8
#define TCOLS  32
#define MROWS  256            // rows (positions) per tile
#define YG     23             // 184/8
#define XG     6              // ceil(184/32)
#define NTILES (B2*YG*XG)     // 2208
#define NTHR   512
#define NCTA   148

#define SXH    16             // TROWS + 8
#define SXW    40             // TCOLS + 8

// ---------------- smem layout (float offsets) ----------------
#define W1F_OFF 0             // [32ks][4jp][32lane][4] = 16384
#define W2F_OFF 16384         // [8ks][4jp][32][4]      = 4096
#define W3F_OFF 20480         // [8ks][1jp][32][4]      = 1024
#define A2F_OFF 21504         // [8ks][512tid][4]       = 16384
#define SX_OFF  37888         // [3][16][40]            = 1920
#define KT_OFF  39808         // 256 ints
#define SB1_OFF 40064         // 64
#define SB2_OFF 40128         // 64
#define SB3_OFF 40192         // 16
#define SMEM_FLOATS 40208     // 160,832 bytes

// ---------------- scratch ----------------
__device__ float g_y[9 * B2 * HP * HP];

static __device__ __forceinline__ uint32_t f2tf32(float v) {
    uint32_t r;
    asm("cvt.rn.tf32.f32 %0, %1;" : "=r"(r) : "f"(v));
    return r;
}

// D += A(16x8,row) * B(8x8,col); tf32 operands, f32 accum.
#define MMA8(c, a0, a1, a2, a3, b0, b1)                                  \
    asm volatile("mma.sync.aligned.m16n8k8.row.col.f32.tf32.tf32.f32 "   \
        "{%0,%1,%2,%3}, {%4,%5,%6,%7}, {%8,%9}, {%0,%1,%2,%3};"          \
        : "+f"((c)[0]), "+f"((c)[1]), "+f"((c)[2]), "+f"((c)[3])         \
        : "r"(a0), "r"(a1), "r"(a2), "r"(a3), "r"(b0), "r"(b1))

#define LDS128U(r0, r1, r2, r3, addr)                                    \
    asm volatile("ld.shared.v4.b32 {%0,%1,%2,%3}, [%4];"                 \
        : "=r"(r0), "=r"(r1), "=r"(r2), "=r"(r3) : "r"(addr))

static __device__ __forceinline__ uint32_t smem_u32(const void* p) {
    uint32_t a;
    asm("{ .reg .u64 t; cvta.to.shared.u64 t, %1; cvt.u32.u64 %0, t; }" : "=r"(a) : "l"(p));
    return a;
}

__global__ __launch_bounds__(NTHR, 1) void mlp_kernel(
    const float* __restrict__ x,
    const float* __restrict__ W1, const float* __restrict__ b1,
    const float* __restrict__ W2, const float* __restrict__ b2,
    const float* __restrict__ W3, const float* __restrict__ b3)
{
    extern __shared__ float smem[];
    uint32_t* su = (uint32_t*)smem;
    const uint32_t sbase = smem_u32(smem);
    const int tid  = threadIdx.x;
    const int lane = tid & 31;
    const int warp = tid >> 5;          // 0..15, owns rows 16w..16w+15
    const int g    = lane >> 2;
    const int tig  = lane & 3;

    // ---------------- one-time prepack ----------------
    // W1 fragment-major: [ks][jp][lane][slot]; slot: {j=2jp:b0,b1, j=2jp+1:b0,b1}
    for (int idx = tid; idx < 16384; idx += NTHR) {
        int slot = idx & 3, ln = (idx >> 2) & 31, jp = (idx >> 7) & 3, ks = idx >> 9;
        int gg = ln >> 2, tt = ln & 3;
        int j = 2 * jp + (slot >> 1);
        int kk = ks * 8 + tt + ((slot & 1) ? 4 : 0);
        int n = j * 8 + gg;
        float v = (n < 50 && kk < 243) ? W1[n * 243 + kk] : 0.f;
        su[W1F_OFF + idx] = f2tf32(v);
    }
    for (int idx = tid; idx < 4096; idx += NTHR) {
        int slot = idx & 3, ln = (idx >> 2) & 31, jp = (idx >> 7) & 3, ks = idx >> 9;
        int gg = ln >> 2, tt = ln & 3;
        int j = 2 * jp + (slot >> 1);
        int kk = ks * 8 + tt + ((slot & 1) ? 4 : 0);
        int n = j * 8 + gg;
        float v = (n < 50 && kk < 50) ? W2[n * 50 + kk] : 0.f;
        su[W2F_OFF + idx] = f2tf32(v);
    }
    for (int idx = tid; idx < 1024; idx += NTHR) {
        int slot = idx & 3, ln = (idx >> 2) & 31, ks = idx >> 7;
        int gg = ln >> 2, tt = ln & 3;
        int j = slot >> 1;
        int kk = ks * 8 + tt + ((slot & 1) ? 4 : 0);
        int n = j * 8 + gg;
        float v = (n < 9 && kk < 50) ? W3[n * 50 + kk] : 0.f;
        su[W3F_OFF + idx] = f2tf32(v);
    }
    {
        int* ktab = (int*)(smem + KT_OFF);
        for (int k = tid; k < 256; k += NTHR) {
            int v = 0;
            if (k < 243) { int c = k / 81, rm = k % 81; v = (c * SXH + rm / 9) * SXW + (rm % 9); }
            ktab[k] = v;
        }
        for (int n = tid; n < 64; n += NTHR) {
            smem[SB1_OFF + n] = (n < 50) ? b1[n] : 0.f;
            smem[SB2_OFF + n] = (n < 50) ? b2[n] : 0.f;
        }
        for (int n = tid; n < 16; n += NTHR) smem[SB3_OFF + n] = (n < 9) ? b3[n] : 0.f;
    }
    __syncthreads();

    const int* ktab = (const int*)(smem + KT_OFF);
    const int rowA = warp * 16 + g;
    const int rowB = rowA + 8;
    // sx per-row base offsets (row -> (py,px) -> smem offset)
    const int srowA = (rowA >> 5) * SXW + (rowA & 31);
    const int srowB = (rowB >> 5) * SXW + (rowB & 31);
    const uint32_t wbase1 = sbase + W1F_OFF * 4 + lane * 16;
    const uint32_t wbase2 = sbase + W2F_OFF * 4 + lane * 16;
    const uint32_t wbase3 = sbase + W3F_OFF * 4 + lane * 16;
    const uint32_t abase2 = sbase + A2F_OFF * 4 + tid * 16;

    // epilogue target addressing for value (row-half ai, j, n)
    const int t01 = 2 * tig;    // n = j*8 + t01 + (d&1)

    for (int t = blockIdx.x; t < NTILES; t += NCTA) {
        const int b  = t / (YG * XG);
        const int rm = t % (YG * XG);
        const int py0 = (rm / XG) * TROWS;
        const int px0 = (rm % XG) * TCOLS;

        __syncthreads();   // everyone done with previous sx
        const float* xb = x + (size_t)b * (C_IN * H_IN * W_IN);
        for (int i = tid; i < C_IN * SXH * SXW; i += NTHR) {
            int q = i % SXW;
            int rr = (i / SXW) % SXH;
            int c = i / (SXH * SXW);
            int gxx = px0 + q;
            smem[SX_OFF + i] = (gxx < W_IN) ? xb[(c * H_IN + (py0 + rr)) * W_IN + gxx] : 0.f;
        }
        __syncthreads();

        const float* sxA = smem + SX_OFF + srowA;
        const float* sxB = smem + SX_OFF + srowB;

        // ================= layer 1: K=243 (30 full ksteps + 1 partial) ========
        float c1[8][4];
        #pragma unroll
        for (int j = 0; j < 8; j++) {
            float bv0 = smem[SB1_OFF + j * 8 + t01];
            float bv1 = smem[SB1_OFF + j * 8 + t01 + 1];
            c1[j][0] = bv0; c1[j][1] = bv1; c1[j][2] = bv0; c1[j][3] = bv1;
        }
        #pragma unroll
        for (int ks = 0; ks < 30; ks++) {
            int ka = ktab[ks * 8 + tig];
            int kb = ktab[ks * 8 + tig + 4];
            uint32_t a0 = f2tf32(sxA[ka]);
            uint32_t a1 = f2tf32(sxB[ka]);
            uint32_t a2 = f2tf32(sxA[kb]);
            uint32_t a3 = f2tf32(sxB[kb]);
            #pragma unroll
            for (int jp = 0; jp < 4; jp++) {
                uint32_t b0, b1r, b2r, b3r;
                LDS128U(b0, b1r, b2r, b3r, wbase1 + (ks * 4 + jp) * 512);
                MMA8(c1[2 * jp],     a0, a1, a2, a3, b0,  b1r);
                MMA8(c1[2 * jp + 1], a0, a1, a2, a3, b2r, b3r);
            }
        }
        {   // ks = 30: k = 240..242 live in a0/a1 (tig<3); a2/a3 all zero-weight
            int ka = ktab[240 + tig];
            uint32_t a0 = 0, a1 = 0;
            if (tig < 3) { a0 = f2tf32(sxA[ka]); a1 = f2tf32(sxB[ka]); }
            #pragma unroll
            for (int jp = 0; jp < 4; jp++) {
                uint32_t b0, b1r, b2r, b3r;
                LDS128U(b0, b1r, b2r, b3r, wbase1 + (30 * 4 + jp) * 512);
                MMA8(c1[2 * jp],     a0, a1, 0u, 0u, b0,  b1r);
                MMA8(c1[2 * jp + 1], a0, a1, 0u, 0u, b2r, b3r);
            }
        }

        // ---- epilogue 1: relu -> tf32 -> A2F fragment-major (n>=50 -> 0) ----
        #pragma unroll
        for (int j = 0; j < 8; j++) {
            #pragma unroll
            for (int d = 0; d < 4; d++) {
                int nr = t01 + (d & 1);             // n - j*8, 0..7
                int n = j * 8 + nr;
                float v = (n < 50) ? fmaxf(c1[j][d], 0.f) : 0.f;
                int slot = ((d >= 2) ? 1 : 0) + 2 * (nr >> 2);
                uint32_t ad = sbase + (A2F_OFF + (j * NTHR + warp * 32 + g * 4 + (nr & 3)) * 4 + slot) * 4;
                uint32_t uv = f2tf32(v);
                asm volatile("st.shared.b32 [%0], %1;" :: "r"(ad), "r"(uv) : "memory");
            }
        }
        __syncwarp();

        // ================= layer 2: K=50 (7 ksteps; ks=6 zero-padded) =========
        float c2[8][4];
        #pragma unroll
        for (int j = 0; j < 8; j++) {
            float bv0 = smem[SB2_OFF + j * 8 + t01];
            float bv1 = smem[SB2_OFF + j * 8 + t01 + 1];
            c2[j][0] = bv0; c2[j][1] = bv1; c2[j][2] = bv0; c2[j][3] = bv1;
        }
        #pragma unroll
        for (int ks = 0; ks < 7; ks++) {
            uint32_t a0, a1, a2, a3;
            LDS128U(a0, a1, a2, a3, abase2 + ks * (NTHR * 16));
            #pragma unroll
            for (int jp = 0; jp < 4; jp++) {
                uint32_t b0, b1r, b2r, b3r;
                LDS128U(b0, b1r, b2r, b3r, wbase2 + (ks * 4 + jp) * 512);
                MMA8(c2[2 * jp],     a0, a1, a2, a3, b0,  b1r);
                MMA8(c2[2 * jp + 1], a0, a1, a2, a3, b2r, b3r);
            }
        }
        __syncwarp();

        // ---- epilogue 2: h2 -> A2F ----
        #pragma unroll
        for (int j = 0; j < 8; j++) {
            #pragma unroll
            for (int d = 0; d < 4; d++) {
                int nr = t01 + (d & 1);
                int n = j * 8 + nr;
                float v = (n < 50) ? fmaxf(c2[j][d], 0.f) : 0.f;
                int slot = ((d >= 2) ? 1 : 0) + 2 * (nr >> 2);
                uint32_t ad = sbase + (A2F_OFF + (j * NTHR + warp * 32 + g * 4 + (nr & 3)) * 4 + slot) * 4;
                uint32_t uv = f2tf32(v);
                asm volatile("st.shared.b32 [%0], %1;" :: "r"(ad), "r"(uv) : "memory");
            }
        }
        __syncwarp();

        // ================= layer 3: K=50, N=16 =================
        float c3[2][4];
        #pragma unroll
        for (int j = 0; j < 2; j++) {
            float bv0 = smem[SB3_OFF + j * 8 + t01];
            float bv1 = smem[SB3_OFF + j * 8 + t01 + 1];
            c3[j][0] = bv0; c3[j][1] = bv1; c3[j][2] = bv0; c3[j][3] = bv1;
        }
        #pragma unroll
        for (int ks = 0; ks < 7; ks++) {
            uint32_t a0, a1, a2, a3;
            LDS128U(a0, a1, a2, a3, abase2 + ks * (NTHR * 16));
            uint32_t b0, b1r, b2r, b3r;
            LDS128U(b0, b1r, b2r, b3r, wbase3 + ks * 512);
            MMA8(c3[0], a0, a1, a2, a3, b0,  b1r);
            MMA8(c3[1], a0, a1, a2, a3, b2r, b3r);
        }

        // ---- epilogue 3: y -> g_y ----
        #pragma unroll
        for (int j = 0; j < 2; j++) {
            #pragma unroll
            for (int d = 0; d < 4; d++) {
                int n = j * 8 + t01 + (d & 1);
                if (n < 9) {
                    int row = (d >= 2) ? rowB : rowA;
                    int py = py0 + (row >> 5);
                    int px = px0 + (row & 31);
                    if (px < HP)
                        g_y[(((size_t)n * B2 + b) * HP + py) * HP + px] = c3[j][d];
                }
            }
        }
    }
}

// ---- fold (overlap-add + divisor) as pure gather ----
__global__ __launch_bounds__(256) void fold_kernel(float* __restrict__ out)
{
    int idx = blockIdx.x * blockDim.x + threadIdx.x;
    const int total = B2 * OUT_H * OUT_H;
    if (idx >= total) return;
    int oj = idx % OUT_H;
    int t  = idx / OUT_H;
    int oi = t % OUT_H;
    int b  = t / OUT_H;

    float acc = 0.f;
    int cnt = 0;
    #pragma unroll
    for (int di = 0; di < KO; di++) {
        int pi = oi - di;
        if (pi < 0 || pi >= HP) continue;
        #pragma unroll
        for (int dj = 0; dj < KO; dj++) {
            int pj = oj - dj;
            if (pj < 0 || pj >= HP) continue;
            acc += g_y[((di * KO + dj) * B2 + b) * (HP * HP) + pi * HP + pj];
            cnt++;
        }
    }
    out[idx] = acc / (float)cnt;
}

extern "C" void kernel_launch(void* const* d_in, const int* in_sizes, int n_in,
                              void* d_out, int out_size)
{
    const float* x  = (const float*)d_in[0];
    const float* W1 = (const float*)d_in[1];
    const float* b1 = (const float*)d_in[2];
    const float* W2 = (const float*)d_in[3];
    const float* b2 = (const float*)d_in[4];
    const float* W3 = (const float*)d_in[5];
    const float* b3 = (const float*)d_in[6];
    float* out = (float*)d_out;

    const int smem_bytes = SMEM_FLOATS * 4;   // 160,832 B
    cudaFuncSetAttribute(mlp_kernel,
                         cudaFuncAttributeMaxDynamicSharedMemorySize, smem_bytes);

    mlp_kernel<<<NCTA, NTHR, smem_bytes>>>(x, W1, b1, W2, b2, W3, b3);

    const int total = B2 * OUT_H * OUT_H;
    fold_kernel<<<(total + 255) / 256, 256>>>(out);
}

// round 11
// speedup vs baseline: 1.5101x; 1.5101x over previous
#include <cuda_runtime.h>
#include <cstdint>

// ---------------- problem constants ----------------
#define KI     9
#define KO     3
#define C_IN   3
#define H_IN   192
#define W_IN   192
#define B2     16
#define HP     184            // H - KI + 1
#define OUT_H  186

// ---------------- tiling ----------------
#define TROWS  8
#define TCOLS  32
#define YG     23             // 184/8
#define XG     6              // ceil(184/32)
#define NTILES (B2*YG*XG)     // 2208
#define NTHR   512
#define NCTA   148

#define SXH    16             // TROWS + 8
#define SXW    40             // TCOLS + 8

// ---------------- smem layout (32-bit word offsets) ----------------
#define W1H_OFF 0             // [16ks][4jp][32lane][4] fp16x2 = 8192
#define W2H_OFF 8192          // [4ks][4jp][32][4]             = 2048
#define W3H_OFF 10240         // [4ks][32][4]                  = 512
#define A2H_OFF 10752         // [32q][264] fp16x2 (stride 264) = 8448
#define SX_OFF  19200         // [3][16][40] f32               = 1920
#define KT_OFF  21120         // 256 ints
#define SB1_OFF 21376         // 64
#define SB2_OFF 21440         // 64
#define SB3_OFF 21504         // 16
#define SMEM_WORDS 21520      // 86,080 bytes

#define A2STR  264            // words; 264%32==8 -> conflict-free

// ---------------- scratch ----------------
__device__ float g_y[9 * B2 * HP * HP];

static __device__ __forceinline__ uint32_t packh2(float lo, float hi) {
    uint32_t r;
    asm("cvt.rn.f16x2.f32 %0, %1, %2;" : "=r"(r) : "f"(hi), "f"(lo));
    return r;
}

// D += A(16x16,row) * B(16x8,col); fp16 operands, f32 accum.
#define MMA16(c, a0, a1, a2, a3, b0, b1)                                     \
    asm volatile("mma.sync.aligned.m16n8k16.row.col.f32.f16.f16.f32 "        \
        "{%0,%1,%2,%3}, {%4,%5,%6,%7}, {%8,%9}, {%0,%1,%2,%3};"              \
        : "+f"((c)[0]), "+f"((c)[1]), "+f"((c)[2]), "+f"((c)[3])             \
        : "r"(a0), "r"(a1), "r"(a2), "r"(a3), "r"(b0), "r"(b1))

#define LDS128U(r0, r1, r2, r3, addr)                                        \
    asm volatile("ld.shared.v4.b32 {%0,%1,%2,%3}, [%4];"                     \
        : "=r"(r0), "=r"(r1), "=r"(r2), "=r"(r3) : "r"(addr))

static __device__ __forceinline__ uint32_t smem_u32(const void* p) {
    uint32_t a;
    asm("{ .reg .u64 t; cvta.to.shared.u64 t, %1; cvt.u32.u64 %0, t; }" : "=r"(a) : "l"(p));
    return a;
}

__global__ __launch_bounds__(NTHR, 1) void mlp_kernel(
    const float* __restrict__ x,
    const float* __restrict__ W1, const float* __restrict__ b1,
    const float* __restrict__ W2, const float* __restrict__ b2,
    const float* __restrict__ W3, const float* __restrict__ b3)
{
    extern __shared__ float smem[];
    uint32_t* su = (uint32_t*)smem;
    const uint32_t sbase = smem_u32(smem);
    const int tid  = threadIdx.x;
    const int lane = tid & 31;
    const int warp = tid >> 5;          // 0..15, owns rows 16w..16w+15
    const int g    = lane >> 2;
    const int tig  = lane & 3;

    // ---------------- one-time weight prepack (fp16x2, fragment-major) ----
    // word(ks,jp,lane,slot): j = 2jp + (slot>>1); k0 = 16ks + 2tig + (slot&1 ? 8:0)
    for (int idx = tid; idx < 8192; idx += NTHR) {          // W1: K=243->256
        int slot = idx & 3, ln = (idx >> 2) & 31, jp = (idx >> 7) & 3, ks = idx >> 9;
        int gg = ln >> 2, tt = ln & 3;
        int n = (2 * jp + (slot >> 1)) * 8 + gg;
        int k0 = ks * 16 + 2 * tt + ((slot & 1) ? 8 : 0);
        float lo = (n < 50 && k0     < 243) ? W1[n * 243 + k0]     : 0.f;
        float hi = (n < 50 && k0 + 1 < 243) ? W1[n * 243 + k0 + 1] : 0.f;
        su[W1H_OFF + idx] = packh2(lo, hi);
    }
    for (int idx = tid; idx < 2048; idx += NTHR) {          // W2: K=50->64
        int slot = idx & 3, ln = (idx >> 2) & 31, jp = (idx >> 7) & 3, ks = idx >> 9;
        int gg = ln >> 2, tt = ln & 3;
        int n = (2 * jp + (slot >> 1)) * 8 + gg;
        int k0 = ks * 16 + 2 * tt + ((slot & 1) ? 8 : 0);
        float lo = (n < 50 && k0     < 50) ? W2[n * 50 + k0]     : 0.f;
        float hi = (n < 50 && k0 + 1 < 50) ? W2[n * 50 + k0 + 1] : 0.f;
        su[W2H_OFF + idx] = packh2(lo, hi);
    }
    for (int idx = tid; idx < 512; idx += NTHR) {           // W3: N=16, K=50->64
        int slot = idx & 3, ln = (idx >> 2) & 31, ks = idx >> 7;
        int gg = ln >> 2, tt = ln & 3;
        int n = (slot >> 1) * 8 + gg;
        int k0 = ks * 16 + 2 * tt + ((slot & 1) ? 8 : 0);
        float lo = (n < 9 && k0     < 50) ? W3[n * 50 + k0]     : 0.f;
        float hi = (n < 9 && k0 + 1 < 50) ? W3[n * 50 + k0 + 1] : 0.f;
        su[W3H_OFF + idx] = packh2(lo, hi);
    }
    {
        int* ktab = (int*)(smem + KT_OFF);
        for (int k = tid; k < 256; k += NTHR) {
            int v = 0;
            if (k < 243) { int c = k / 81, rm = k % 81; v = (c * SXH + rm / 9) * SXW + (rm % 9); }
            ktab[k] = v;
        }
        for (int n = tid; n < 64; n += NTHR) {
            smem[SB1_OFF + n] = (n < 50) ? b1[n] : 0.f;
            smem[SB2_OFF + n] = (n < 50) ? b2[n] : 0.f;
        }
        for (int n = tid; n < 16; n += NTHR) smem[SB3_OFF + n] = (n < 9) ? b3[n] : 0.f;
    }
    __syncthreads();

    const int* ktab = (const int*)(smem + KT_OFF);
    const int rowA = warp * 16 + g;
    const int rowB = rowA + 8;
    const int srowA = (rowA >> 5) * SXW + (rowA & 31);
    const int srowB = (rowB >> 5) * SXW + (rowB & 31);
    const uint32_t wbase1 = sbase + W1H_OFF * 4 + lane * 16;
    const uint32_t wbase2 = sbase + W2H_OFF * 4 + lane * 16;
    const uint32_t wbase3 = sbase + W3H_OFF * 4 + lane * 16;
    const int t01 = 2 * tig;

    for (int t = blockIdx.x; t < NTILES; t += NCTA) {
        const int b  = t / (YG * XG);
        const int rm = t % (YG * XG);
        const int py0 = (rm / XG) * TROWS;
        const int px0 = (rm % XG) * TCOLS;

        __syncthreads();   // everyone done with previous sx
        const float* xb = x + (size_t)b * (C_IN * H_IN * W_IN);
        for (int i = tid; i < C_IN * SXH * SXW; i += NTHR) {
            int q = i % SXW;
            int rr = (i / SXW) % SXH;
            int c = i / (SXH * SXW);
            int gxx = px0 + q;
            smem[SX_OFF + i] = (gxx < W_IN) ? xb[(c * H_IN + (py0 + rr)) * W_IN + gxx] : 0.f;
        }
        __syncthreads();

        const float* sxA = smem + SX_OFF + srowA;
        const float* sxB = smem + SX_OFF + srowB;

        // ================= layer 1: K=243->256, 16 ksteps =================
        float c1[8][4];
        #pragma unroll
        for (int j = 0; j < 8; j++) {
            float bv0 = smem[SB1_OFF + j * 8 + t01];
            float bv1 = smem[SB1_OFF + j * 8 + t01 + 1];
            c1[j][0] = bv0; c1[j][1] = bv1; c1[j][2] = bv0; c1[j][3] = bv1;
        }
        #pragma unroll
        for (int ks = 0; ks < 16; ks++) {
            const int k0 = ks * 16;
            int kA0 = ktab[k0 + t01],     kA1 = ktab[k0 + t01 + 1];
            int kB0 = ktab[k0 + t01 + 8], kB1 = ktab[k0 + t01 + 9];
            uint32_t a0 = packh2(sxA[kA0], sxA[kA1]);
            uint32_t a1 = packh2(sxB[kA0], sxB[kA1]);
            uint32_t a2 = packh2(sxA[kB0], sxA[kB1]);
            uint32_t a3 = packh2(sxB[kB0], sxB[kB1]);
            #pragma unroll
            for (int jp = 0; jp < 4; jp++) {
                uint32_t b0, b1r, b2r, b3r;
                LDS128U(b0, b1r, b2r, b3r, wbase1 + (ks * 4 + jp) * 512);
                MMA16(c1[2 * jp],     a0, a1, a2, a3, b0,  b1r);
                MMA16(c1[2 * jp + 1], a0, a1, a2, a3, b2r, b3r);
            }
        }

        // ---- epilogue 1: relu -> fp16x2 n-pairs -> A2H (zeros for n>=50) ----
        #pragma unroll
        for (int j = 0; j < 8; j++) {
            int n0 = j * 8 + t01;
            int q = j * 4 + tig;
            float vA0 = 0.f, vA1 = 0.f, vB0 = 0.f, vB1 = 0.f;
            if (n0 < 50) {
                vA0 = fmaxf(c1[j][0], 0.f); vA1 = fmaxf(c1[j][1], 0.f);
                vB0 = fmaxf(c1[j][2], 0.f); vB1 = fmaxf(c1[j][3], 0.f);
            }
            su[A2H_OFF + q * A2STR + rowA] = packh2(vA0, vA1);
            su[A2H_OFF + q * A2STR + rowB] = packh2(vB0, vB1);
        }
        __syncwarp();

        // ================= layer 2: K=50->64, 4 ksteps =================
        float c2[8][4];
        #pragma unroll
        for (int j = 0; j < 8; j++) {
            float bv0 = smem[SB2_OFF + j * 8 + t01];
            float bv1 = smem[SB2_OFF + j * 8 + t01 + 1];
            c2[j][0] = bv0; c2[j][1] = bv1; c2[j][2] = bv0; c2[j][3] = bv1;
        }
        #pragma unroll
        for (int ks = 0; ks < 4; ks++) {
            int qb = 8 * ks + tig;
            uint32_t a0 = su[A2H_OFF + qb * A2STR + rowA];
            uint32_t a1 = su[A2H_OFF + qb * A2STR + rowB];
            uint32_t a2 = su[A2H_OFF + (qb + 4) * A2STR + rowA];
            uint32_t a3 = su[A2H_OFF + (qb + 4) * A2STR + rowB];
            #pragma unroll
            for (int jp = 0; jp < 4; jp++) {
                uint32_t b0, b1r, b2r, b3r;
                LDS128U(b0, b1r, b2r, b3r, wbase2 + (ks * 4 + jp) * 512);
                MMA16(c2[2 * jp],     a0, a1, a2, a3, b0,  b1r);
                MMA16(c2[2 * jp + 1], a0, a1, a2, a3, b2r, b3r);
            }
        }
        __syncwarp();

        // ---- epilogue 2: h2 -> A2H ----
        #pragma unroll
        for (int j = 0; j < 8; j++) {
            int n0 = j * 8 + t01;
            int q = j * 4 + tig;
            float vA0 = 0.f, vA1 = 0.f, vB0 = 0.f, vB1 = 0.f;
            if (n0 < 50) {
                vA0 = fmaxf(c2[j][0], 0.f); vA1 = fmaxf(c2[j][1], 0.f);
                vB0 = fmaxf(c2[j][2], 0.f); vB1 = fmaxf(c2[j][3], 0.f);
            }
            su[A2H_OFF + q * A2STR + rowA] = packh2(vA0, vA1);
            su[A2H_OFF + q * A2STR + rowB] = packh2(vB0, vB1);
        }
        __syncwarp();

        // ================= layer 3: K=50->64, N=16 =================
        float c3[2][4];
        #pragma unroll
        for (int j = 0; j < 2; j++) {
            float bv0 = smem[SB3_OFF + j * 8 + t01];
            float bv1 = smem[SB3_OFF + j * 8 + t01 + 1];
            c3[j][0] = bv0; c3[j][1] = bv1; c3[j][2] = bv0; c3[j][3] = bv1;
        }
        #pragma unroll
        for (int ks = 0; ks < 4; ks++) {
            int qb = 8 * ks + tig;
            uint32_t a0 = su[A2H_OFF + qb * A2STR + rowA];
            uint32_t a1 = su[A2H_OFF + qb * A2STR + rowB];
            uint32_t a2 = su[A2H_OFF + (qb + 4) * A2STR + rowA];
            uint32_t a3 = su[A2H_OFF + (qb + 4) * A2STR + rowB];
            uint32_t b0, b1r, b2r, b3r;
            LDS128U(b0, b1r, b2r, b3r, wbase3 + ks * 512);
            MMA16(c3[0], a0, a1, a2, a3, b0,  b1r);
            MMA16(c3[1], a0, a1, a2, a3, b2r, b3r);
        }

        // ---- epilogue 3: y -> g_y ----
        #pragma unroll
        for (int j = 0; j < 2; j++) {
            #pragma unroll
            for (int d = 0; d < 4; d++) {
                int n = j * 8 + t01 + (d & 1);
                if (n < 9) {
                    int row = (d >= 2) ? rowB : rowA;
                    int py = py0 + (row >> 5);
                    int px = px0 + (row & 31);
                    if (px < HP)
                        g_y[(((size_t)n * B2 + b) * HP + py) * HP + px] = c3[j][d];
                }
            }
        }
    }
}

// ---- fold (overlap-add + divisor) as pure gather ----
__global__ __launch_bounds__(256) void fold_kernel(float* __restrict__ out)
{
    int idx = blockIdx.x * blockDim.x + threadIdx.x;
    const int total = B2 * OUT_H * OUT_H;
    if (idx >= total) return;
    int oj = idx % OUT_H;
    int t  = idx / OUT_H;
    int oi = t % OUT_H;
    int b  = t / OUT_H;

    float acc = 0.f;
    int cnt = 0;
    #pragma unroll
    for (int di = 0; di < KO; di++) {
        int pi = oi - di;
        if (pi < 0 || pi >= HP) continue;
        #pragma unroll
        for (int dj = 0; dj < KO; dj++) {
            int pj = oj - dj;
            if (pj < 0 || pj >= HP) continue;
            acc += g_y[((di * KO + dj) * B2 + b) * (HP * HP) + pi * HP + pj];
            cnt++;
        }
    }
    out[idx] = acc / (float)cnt;
}

extern "C" void kernel_launch(void* const* d_in, const int* in_sizes, int n_in,
                              void* d_out, int out_size)
{
    const float* x  = (const float*)d_in[0];
    const float* W1 = (const float*)d_in[1];
    const float* b1 = (const float*)d_in[2];
    const float* W2 = (const float*)d_in[3];
    const float* b2 = (const float*)d_in[4];
    const float* W3 = (const float*)d_in[5];
    const float* b3 = (const float*)d_in[6];
    float* out = (float*)d_out;

    const int smem_bytes = SMEM_WORDS * 4;   // 86,080 B
    cudaFuncSetAttribute(mlp_kernel,
                         cudaFuncAttributeMaxDynamicSharedMemorySize, smem_bytes);

    mlp_kernel<<<NCTA, NTHR, smem_bytes>>>(x, W1, b1, W2, b2, W3, b3);

    const int total = B2 * OUT_H * OUT_H;
    fold_kernel<<<(total + 255) / 256, 256>>>(out);
}

// round 12
// speedup vs baseline: 1.9931x; 1.3198x over previous
#include <cuda_runtime.h>
#include <cstdint>

// ---------------- problem constants ----------------
#define KI     9
#define KO     3
#define C_IN   3
#define H_IN   192
#define W_IN   192
#define B2     16
#define HP     184            // H - KI + 1
#define OUT_H  186

// ---------------- tiling ----------------
#define TROWS  8
#define TCOLS  32
#define YG     23             // 184/8
#define XG     6              // ceil(184/32)
#define NTILES (B2*YG*XG)     // 2208
#define NTHR   256            // 8 warps; each warp owns 32 rows (2 blocks)
#define NCTA   148

#define SXH    16             // TROWS + 8
#define SXW    40             // TCOLS + 8

// ---------------- smem layout (32-bit word offsets) ----------------
#define W1H_OFF 0             // [16ks][4jp][32lane][4] fp16x2 = 8192
#define W2H_OFF 8192          // [4ks][4jp][32][4]             = 2048
#define W3H_OFF 10240         // [4ks][32][4]                  = 512
#define A2H_OFF 10752         // [32q][264] fp16x2             = 8448
#define SX_OFF  19200         // [3][16][40] f32               = 1920
#define KT_OFF  21120         // 256 ints
#define SB1_OFF 21376         // 64
#define SB2_OFF 21440         // 64
#define SB3_OFF 21504         // 16
#define SMEM_WORDS 21520      // 86,080 bytes

#define A2STR  264            // words; 264%32==8 -> conflict-free

// ---------------- scratch ----------------
__device__ float g_y[9 * B2 * HP * HP];

static __device__ __forceinline__ uint32_t packh2(float lo, float hi) {
    uint32_t r;
    asm("cvt.rn.f16x2.f32 %0, %1, %2;" : "=r"(r) : "f"(hi), "f"(lo));
    return r;
}

// D += A(16x16,row) * B(16x8,col); fp16 operands, f32 accum.
#define MMA16(c, a0, a1, a2, a3, b0, b1)                                     \
    asm volatile("mma.sync.aligned.m16n8k16.row.col.f32.f16.f16.f32 "        \
        "{%0,%1,%2,%3}, {%4,%5,%6,%7}, {%8,%9}, {%0,%1,%2,%3};"              \
        : "+f"((c)[0]), "+f"((c)[1]), "+f"((c)[2]), "+f"((c)[3])             \
        : "r"(a0), "r"(a1), "r"(a2), "r"(a3), "r"(b0), "r"(b1))

#define LDS128U(r0, r1, r2, r3, addr)                                        \
    asm volatile("ld.shared.v4.b32 {%0,%1,%2,%3}, [%4];"                     \
        : "=r"(r0), "=r"(r1), "=r"(r2), "=r"(r3) : "r"(addr))

static __device__ __forceinline__ uint32_t smem_u32(const void* p) {
    uint32_t a;
    asm("{ .reg .u64 t; cvta.to.shared.u64 t, %1; cvt.u32.u64 %0, t; }" : "=r"(a) : "l"(p));
    return a;
}

__global__ __launch_bounds__(NTHR, 1) void mlp_kernel(
    const float* __restrict__ x,
    const float* __restrict__ W1, const float* __restrict__ b1,
    const float* __restrict__ W2, const float* __restrict__ b2,
    const float* __restrict__ W3, const float* __restrict__ b3)
{
    extern __shared__ float smem[];
    uint32_t* su = (uint32_t*)smem;
    const uint32_t sbase = smem_u32(smem);
    const int tid  = threadIdx.x;
    const int lane = tid & 31;
    const int warp = tid >> 5;          // 0..7, owns rows 32w..32w+31
    const int g    = lane >> 2;
    const int tig  = lane & 3;

    // ---------------- one-time prepack (fp16x2, fragment-major) ----------
    for (int idx = tid; idx < 8192; idx += NTHR) {          // W1: K=243->256
        int slot = idx & 3, ln = (idx >> 2) & 31, jp = (idx >> 7) & 3, ks = idx >> 9;
        int gg = ln >> 2, tt = ln & 3;
        int n = (2 * jp + (slot >> 1)) * 8 + gg;
        int k0 = ks * 16 + 2 * tt + ((slot & 1) ? 8 : 0);
        float lo = (n < 50 && k0     < 243) ? W1[n * 243 + k0]     : 0.f;
        float hi = (n < 50 && k0 + 1 < 243) ? W1[n * 243 + k0 + 1] : 0.f;
        su[W1H_OFF + idx] = packh2(lo, hi);
    }
    for (int idx = tid; idx < 2048; idx += NTHR) {          // W2: K=50->64
        int slot = idx & 3, ln = (idx >> 2) & 31, jp = (idx >> 7) & 3, ks = idx >> 9;
        int gg = ln >> 2, tt = ln & 3;
        int n = (2 * jp + (slot >> 1)) * 8 + gg;
        int k0 = ks * 16 + 2 * tt + ((slot & 1) ? 8 : 0);
        float lo = (n < 50 && k0     < 50) ? W2[n * 50 + k0]     : 0.f;
        float hi = (n < 50 && k0 + 1 < 50) ? W2[n * 50 + k0 + 1] : 0.f;
        su[W2H_OFF + idx] = packh2(lo, hi);
    }
    for (int idx = tid; idx < 512; idx += NTHR) {           // W3: N=16, K=50->64
        int slot = idx & 3, ln = (idx >> 2) & 31, ks = idx >> 7;
        int gg = ln >> 2, tt = ln & 3;
        int n = (slot >> 1) * 8 + gg;
        int k0 = ks * 16 + 2 * tt + ((slot & 1) ? 8 : 0);
        float lo = (n < 9 && k0     < 50) ? W3[n * 50 + k0]     : 0.f;
        float hi = (n < 9 && k0 + 1 < 50) ? W3[n * 50 + k0 + 1] : 0.f;
        su[W3H_OFF + idx] = packh2(lo, hi);
    }
    for (int idx = tid; idx < 8448; idx += NTHR)            // zero A2H once
        su[A2H_OFF + idx] = 0;
    {
        int* ktab = (int*)(smem + KT_OFF);
        for (int k = tid; k < 256; k += NTHR) {
            int v = 0;
            if (k < 243) { int c = k / 81, rm = k % 81; v = (c * SXH + rm / 9) * SXW + (rm % 9); }
            ktab[k] = v;
        }
        for (int n = tid; n < 64; n += NTHR) {
            smem[SB1_OFF + n] = (n < 50) ? b1[n] : 0.f;
            smem[SB2_OFF + n] = (n < 50) ? b2[n] : 0.f;
        }
        for (int n = tid; n < 16; n += NTHR) smem[SB3_OFF + n] = (n < 9) ? b3[n] : 0.f;
    }
    __syncthreads();

    const int* ktab = (const int*)(smem + KT_OFF);
    // warp's 4 row anchors: blk0 -> rows r0, r0+8; blk1 -> r0+16, r0+24
    const int r0 = warp * 32 + g;
    const int rows[4] = { r0, r0 + 8, r0 + 16, r0 + 24 };
    const float* sxr[4];
    const uint32_t wbase1 = sbase + W1H_OFF * 4 + lane * 16;
    const uint32_t wbase2 = sbase + W2H_OFF * 4 + lane * 16;
    const uint32_t wbase3 = sbase + W3H_OFF * 4 + lane * 16;
    const int t01 = 2 * tig;

    for (int t = blockIdx.x; t < NTILES; t += NCTA) {
        const int b  = t / (YG * XG);
        const int rm = t % (YG * XG);
        const int py0 = (rm / XG) * TROWS;
        const int px0 = (rm % XG) * TCOLS;

        __syncthreads();   // everyone done with previous sx
        const float* xb = x + (size_t)b * (C_IN * H_IN * W_IN);
        for (int i = tid; i < C_IN * SXH * SXW; i += NTHR) {
            int q = i % SXW;
            int rr = (i / SXW) % SXH;
            int c = i / (SXH * SXW);
            int gxx = px0 + q;
            smem[SX_OFF + i] = (gxx < W_IN) ? xb[(c * H_IN + (py0 + rr)) * W_IN + gxx] : 0.f;
        }
        __syncthreads();

        #pragma unroll
        for (int r = 0; r < 4; r++)
            sxr[r] = smem + SX_OFF + (rows[r] >> 5) * SXW + (rows[r] & 31);

        // ================= layer 1: K=256 (16 ksteps), N=56 (7 j) =========
        float c1[2][7][4];
        #pragma unroll
        for (int j = 0; j < 7; j++) {
            float bv0 = smem[SB1_OFF + j * 8 + t01];
            float bv1 = smem[SB1_OFF + j * 8 + t01 + 1];
            #pragma unroll
            for (int blk = 0; blk < 2; blk++) {
                c1[blk][j][0] = bv0; c1[blk][j][1] = bv1;
                c1[blk][j][2] = bv0; c1[blk][j][3] = bv1;
            }
        }
        #pragma unroll
        for (int ks = 0; ks < 16; ks++) {
            const int k0 = ks * 16;
            int kA0 = ktab[k0 + t01],     kA1 = ktab[k0 + t01 + 1];
            int kB0 = ktab[k0 + t01 + 8], kB1 = ktab[k0 + t01 + 9];
            uint32_t a0 = packh2(sxr[0][kA0], sxr[0][kA1]);
            uint32_t a1 = packh2(sxr[1][kA0], sxr[1][kA1]);
            uint32_t a2 = packh2(sxr[0][kB0], sxr[0][kB1]);
            uint32_t a3 = packh2(sxr[1][kB0], sxr[1][kB1]);
            uint32_t a4 = packh2(sxr[2][kA0], sxr[2][kA1]);
            uint32_t a5 = packh2(sxr[3][kA0], sxr[3][kA1]);
            uint32_t a6 = packh2(sxr[2][kB0], sxr[2][kB1]);
            uint32_t a7 = packh2(sxr[3][kB0], sxr[3][kB1]);
            #pragma unroll
            for (int jp = 0; jp < 4; jp++) {
                uint32_t b0, b1r, b2r, b3r;
                LDS128U(b0, b1r, b2r, b3r, wbase1 + (ks * 4 + jp) * 512);
                MMA16(c1[0][2 * jp], a0, a1, a2, a3, b0, b1r);
                MMA16(c1[1][2 * jp], a4, a5, a6, a7, b0, b1r);
                if (jp < 3) {
                    MMA16(c1[0][2 * jp + 1], a0, a1, a2, a3, b2r, b3r);
                    MMA16(c1[1][2 * jp + 1], a4, a5, a6, a7, b2r, b3r);
                }
            }
        }

        // ---- epilogue 1: relu -> fp16x2 n-pairs -> A2H ----
        #pragma unroll
        for (int blk = 0; blk < 2; blk++) {
            #pragma unroll
            for (int j = 0; j < 7; j++) {
                int n0 = j * 8 + t01;
                int q = j * 4 + tig;
                float vA0 = 0.f, vA1 = 0.f, vB0 = 0.f, vB1 = 0.f;
                if (n0 < 50) {
                    vA0 = fmaxf(c1[blk][j][0], 0.f);
                    vA1 = (n0 + 1 < 50) ? fmaxf(c1[blk][j][1], 0.f) : 0.f;
                    vB0 = fmaxf(c1[blk][j][2], 0.f);
                    vB1 = (n0 + 1 < 50) ? fmaxf(c1[blk][j][3], 0.f) : 0.f;
                }
                su[A2H_OFF + q * A2STR + rows[blk * 2]]     = packh2(vA0, vA1);
                su[A2H_OFF + q * A2STR + rows[blk * 2 + 1]] = packh2(vB0, vB1);
            }
        }
        __syncwarp();

        // ================= layer 2: K=64 (4 ksteps), N=56 =================
        float c2[2][7][4];
        #pragma unroll
        for (int j = 0; j < 7; j++) {
            float bv0 = smem[SB2_OFF + j * 8 + t01];
            float bv1 = smem[SB2_OFF + j * 8 + t01 + 1];
            #pragma unroll
            for (int blk = 0; blk < 2; blk++) {
                c2[blk][j][0] = bv0; c2[blk][j][1] = bv1;
                c2[blk][j][2] = bv0; c2[blk][j][3] = bv1;
            }
        }
        #pragma unroll
        for (int ks = 0; ks < 4; ks++) {
            int qb = 8 * ks + tig;
            uint32_t a0 = su[A2H_OFF + qb * A2STR + rows[0]];
            uint32_t a1 = su[A2H_OFF + qb * A2STR + rows[1]];
            uint32_t a2 = su[A2H_OFF + (qb + 4) * A2STR + rows[0]];
            uint32_t a3 = su[A2H_OFF + (qb + 4) * A2STR + rows[1]];
            uint32_t a4 = su[A2H_OFF + qb * A2STR + rows[2]];
            uint32_t a5 = su[A2H_OFF + qb * A2STR + rows[3]];
            uint32_t a6 = su[A2H_OFF + (qb + 4) * A2STR + rows[2]];
            uint32_t a7 = su[A2H_OFF + (qb + 4) * A2STR + rows[3]];
            #pragma unroll
            for (int jp = 0; jp < 4; jp++) {
                uint32_t b0, b1r, b2r, b3r;
                LDS128U(b0, b1r, b2r, b3r, wbase2 + (ks * 4 + jp) * 512);
                MMA16(c2[0][2 * jp], a0, a1, a2, a3, b0, b1r);
                MMA16(c2[1][2 * jp], a4, a5, a6, a7, b0, b1r);
                if (jp < 3) {
                    MMA16(c2[0][2 * jp + 1], a0, a1, a2, a3, b2r, b3r);
                    MMA16(c2[1][2 * jp + 1], a4, a5, a6, a7, b2r, b3r);
                }
            }
        }
        __syncwarp();

        // ---- epilogue 2: h2 -> A2H ----
        #pragma unroll
        for (int blk = 0; blk < 2; blk++) {
            #pragma unroll
            for (int j = 0; j < 7; j++) {
                int n0 = j * 8 + t01;
                int q = j * 4 + tig;
                float vA0 = 0.f, vA1 = 0.f, vB0 = 0.f, vB1 = 0.f;
                if (n0 < 50) {
                    vA0 = fmaxf(c2[blk][j][0], 0.f);
                    vA1 = (n0 + 1 < 50) ? fmaxf(c2[blk][j][1], 0.f) : 0.f;
                    vB0 = fmaxf(c2[blk][j][2], 0.f);
                    vB1 = (n0 + 1 < 50) ? fmaxf(c2[blk][j][3], 0.f) : 0.f;
                }
                su[A2H_OFF + q * A2STR + rows[blk * 2]]     = packh2(vA0, vA1);
                su[A2H_OFF + q * A2STR + rows[blk * 2 + 1]] = packh2(vB0, vB1);
            }
        }
        __syncwarp();

        // ================= layer 3: K=64, N=16 =================
        float c3[2][2][4];
        #pragma unroll
        for (int j = 0; j < 2; j++) {
            float bv0 = smem[SB3_OFF + j * 8 + t01];
            float bv1 = smem[SB3_OFF + j * 8 + t01 + 1];
            #pragma unroll
            for (int blk = 0; blk < 2; blk++) {
                c3[blk][j][0] = bv0; c3[blk][j][1] = bv1;
                c3[blk][j][2] = bv0; c3[blk][j][3] = bv1;
            }
        }
        #pragma unroll
        for (int ks = 0; ks < 4; ks++) {
            int qb = 8 * ks + tig;
            uint32_t a0 = su[A2H_OFF + qb * A2STR + rows[0]];
            uint32_t a1 = su[A2H_OFF + qb * A2STR + rows[1]];
            uint32_t a2 = su[A2H_OFF + (qb + 4) * A2STR + rows[0]];
            uint32_t a3 = su[A2H_OFF + (qb + 4) * A2STR + rows[1]];
            uint32_t a4 = su[A2H_OFF + qb * A2STR + rows[2]];
            uint32_t a5 = su[A2H_OFF + qb * A2STR + rows[3]];
            uint32_t a6 = su[A2H_OFF + (qb + 4) * A2STR + rows[2]];
            uint32_t a7 = su[A2H_OFF + (qb + 4) * A2STR + rows[3]];
            uint32_t b0, b1r, b2r, b3r;
            LDS128U(b0, b1r, b2r, b3r, wbase3 + ks * 512);
            MMA16(c3[0][0], a0, a1, a2, a3, b0,  b1r);
            MMA16(c3[1][0], a4, a5, a6, a7, b0,  b1r);
            MMA16(c3[0][1], a0, a1, a2, a3, b2r, b3r);
            MMA16(c3[1][1], a4, a5, a6, a7, b2r, b3r);
        }

        // ---- epilogue 3: y -> g_y ----
        #pragma unroll
        for (int blk = 0; blk < 2; blk++) {
            #pragma unroll
            for (int j = 0; j < 2; j++) {
                #pragma unroll
                for (int d = 0; d < 4; d++) {
                    int n = j * 8 + t01 + (d & 1);
                    if (n < 9) {
                        int row = rows[blk * 2 + ((d >= 2) ? 1 : 0)];
                        int py = py0 + (row >> 5);
                        int px = px0 + (row & 31);
                        if (px < HP)
                            g_y[(((size_t)n * B2 + b) * HP + py) * HP + px] = c3[blk][j][d];
                    }
                }
            }
        }
    }
}

// ---- fold (overlap-add + divisor) as pure gather ----
__global__ __launch_bounds__(256) void fold_kernel(float* __restrict__ out)
{
    int idx = blockIdx.x * blockDim.x + threadIdx.x;
    const int total = B2 * OUT_H * OUT_H;
    if (idx >= total) return;
    int oj = idx % OUT_H;
    int t  = idx / OUT_H;
    int oi = t % OUT_H;
    int b  = t / OUT_H;

    float acc = 0.f;
    int cnt = 0;
    #pragma unroll
    for (int di = 0; di < KO; di++) {
        int pi = oi - di;
        if (pi < 0 || pi >= HP) continue;
        #pragma unroll
        for (int dj = 0; dj < KO; dj++) {
            int pj = oj - dj;
            if (pj < 0 || pj >= HP) continue;
            acc += g_y[((di * KO + dj) * B2 + b) * (HP * HP) + pi * HP + pj];
            cnt++;
        }
    }
    out[idx] = acc / (float)cnt;
}

extern "C" void kernel_launch(void* const* d_in, const int* in_sizes, int n_in,
                              void* d_out, int out_size)
{
    const float* x  = (const float*)d_in[0];
    const float* W1 = (const float*)d_in[1];
    const float* b1 = (const float*)d_in[2];
    const float* W2 = (const float*)d_in[3];
    const float* b2 = (const float*)d_in[4];
    const float* W3 = (const float*)d_in[5];
    const float* b3 = (const float*)d_in[6];
    float* out = (float*)d_out;

    const int smem_bytes = SMEM_WORDS * 4;   // 86,080 B
    cudaFuncSetAttribute(mlp_kernel,
                         cudaFuncAttributeMaxDynamicSharedMemorySize, smem_bytes);

    mlp_kernel<<<NCTA, NTHR, smem_bytes>>>(x, W1, b1, W2, b2, W3, b3);

    const int total = B2 * OUT_H * OUT_H;
    fold_kernel<<<(total + 255) / 256, 256>>>(out);
}

// round 13
// speedup vs baseline: 2.0057x; 1.0063x over previous
#include <cuda_runtime.h>
#include <cstdint>

// ---------------- problem constants ----------------
#define KI     9
#define KO     3
#define C_IN   3
#define H_IN   192
#define W_IN   192
#define B2     16
#define HP     184            // H - KI + 1
#define OUT_H  186

// ---------------- tiling ----------------
#define TROWS  8
#define TCOLS  32
#define YG     23             // 184/8
#define XG     6              // ceil(184/32)
#define NTILES (B2*YG*XG)     // 2208
#define NTHR   256            // 8 warps; each warp owns 32 rows (2 blocks)
#define NCTA   148

#define SXH    16             // TROWS + 8
#define SXW    40             // TCOLS + 8

// ---------------- smem layout (32-bit word offsets) ----------------
#define W1H_OFF 0             // [16ks][4jp][32lane][4] fp16x2 = 8192
#define W2H_OFF 8192          // [4ks][4jp][32][4]             = 2048
#define W3H_OFF 10240         // [4ks][32][4]                  = 512
#define A2H_OFF 10752         // [32q][264] fp16x2             = 8448
#define SX_OFF  19200         // [3][16][40] f32               = 1920
#define KT_OFF  21120         // 256 ints
#define SB1_OFF 21376         // 64
#define SB2_OFF 21440         // 64
#define SB3_OFF 21504         // 16
#define SMEM_WORDS 21520      // 86,080 bytes

#define A2STR  264            // words; 264%32==8 -> conflict-free

// ---------------- scratch ----------------
__device__ float g_y[9 * B2 * HP * HP];

static __device__ __forceinline__ uint32_t packh2(float lo, float hi) {
    uint32_t r;
    asm("cvt.rn.f16x2.f32 %0, %1, %2;" : "=r"(r) : "f"(hi), "f"(lo));
    return r;
}

// D += A(16x16,row) * B(16x8,col); fp16 operands, f32 accum.
#define MMA16(c, a0, a1, a2, a3, b0, b1)                                     \
    asm volatile("mma.sync.aligned.m16n8k16.row.col.f32.f16.f16.f32 "        \
        "{%0,%1,%2,%3}, {%4,%5,%6,%7}, {%8,%9}, {%0,%1,%2,%3};"              \
        : "+f"((c)[0]), "+f"((c)[1]), "+f"((c)[2]), "+f"((c)[3])             \
        : "r"(a0), "r"(a1), "r"(a2), "r"(a3), "r"(b0), "r"(b1))

#define LDS128U(r0, r1, r2, r3, addr)                                        \
    asm volatile("ld.shared.v4.b32 {%0,%1,%2,%3}, [%4];"                     \
        : "=r"(r0), "=r"(r1), "=r"(r2), "=r"(r3) : "r"(addr))

static __device__ __forceinline__ uint32_t smem_u32(const void* p) {
    uint32_t a;
    asm("{ .reg .u64 t; cvta.to.shared.u64 t, %1; cvt.u32.u64 %0, t; }" : "=r"(a) : "l"(p));
    return a;
}

__global__ __launch_bounds__(NTHR, 1) void mlp_kernel(
    const float* __restrict__ x,
    const float* __restrict__ W1, const float* __restrict__ b1,
    const float* __restrict__ W2, const float* __restrict__ b2,
    const float* __restrict__ W3, const float* __restrict__ b3)
{
    extern __shared__ float smem[];
    uint32_t* su = (uint32_t*)smem;
    const uint32_t sbase = smem_u32(smem);
    const int tid  = threadIdx.x;
    const int lane = tid & 31;
    const int warp = tid >> 5;          // 0..7, owns rows 32w..32w+31
    const int g    = lane >> 2;
    const int tig  = lane & 3;

    // ---------------- one-time prepack (fp16x2, fragment-major) ----------
    for (int idx = tid; idx < 8192; idx += NTHR) {          // W1: K=243->256
        int slot = idx & 3, ln = (idx >> 2) & 31, jp = (idx >> 7) & 3, ks = idx >> 9;
        int gg = ln >> 2, tt = ln & 3;
        int n = (2 * jp + (slot >> 1)) * 8 + gg;
        int k0 = ks * 16 + 2 * tt + ((slot & 1) ? 8 : 0);
        float lo = (n < 50 && k0     < 243) ? W1[n * 243 + k0]     : 0.f;
        float hi = (n < 50 && k0 + 1 < 243) ? W1[n * 243 + k0 + 1] : 0.f;
        su[W1H_OFF + idx] = packh2(lo, hi);
    }
    for (int idx = tid; idx < 2048; idx += NTHR) {          // W2: K=50->64
        int slot = idx & 3, ln = (idx >> 2) & 31, jp = (idx >> 7) & 3, ks = idx >> 9;
        int gg = ln >> 2, tt = ln & 3;
        int n = (2 * jp + (slot >> 1)) * 8 + gg;
        int k0 = ks * 16 + 2 * tt + ((slot & 1) ? 8 : 0);
        float lo = (n < 50 && k0     < 50) ? W2[n * 50 + k0]     : 0.f;
        float hi = (n < 50 && k0 + 1 < 50) ? W2[n * 50 + k0 + 1] : 0.f;
        su[W2H_OFF + idx] = packh2(lo, hi);
    }
    for (int idx = tid; idx < 512; idx += NTHR) {           // W3: N=16, K=50->64
        int slot = idx & 3, ln = (idx >> 2) & 31, ks = idx >> 7;
        int gg = ln >> 2, tt = ln & 3;
        int n = (slot >> 1) * 8 + gg;
        int k0 = ks * 16 + 2 * tt + ((slot & 1) ? 8 : 0);
        float lo = (n < 9 && k0     < 50) ? W3[n * 50 + k0]     : 0.f;
        float hi = (n < 9 && k0 + 1 < 50) ? W3[n * 50 + k0 + 1] : 0.f;
        su[W3H_OFF + idx] = packh2(lo, hi);
    }
    for (int idx = tid; idx < 8448; idx += NTHR)            // zero A2H once
        su[A2H_OFF + idx] = 0;
    {
        int* ktab = (int*)(smem + KT_OFF);
        for (int k = tid; k < 256; k += NTHR) {
            int v = 0;
            if (k < 243) { int c = k / 81, rm = k % 81; v = (c * SXH + rm / 9) * SXW + (rm % 9); }
            ktab[k] = v;
        }
        for (int n = tid; n < 64; n += NTHR) {
            smem[SB1_OFF + n] = (n < 50) ? b1[n] : 0.f;
            smem[SB2_OFF + n] = (n < 50) ? b2[n] : 0.f;
        }
        for (int n = tid; n < 16; n += NTHR) smem[SB3_OFF + n] = (n < 9) ? b3[n] : 0.f;
    }
    __syncthreads();

    const int* ktab = (const int*)(smem + KT_OFF);
    // warp's 4 row anchors: blk0 -> rows r0, r0+8; blk1 -> r0+16, r0+24
    const int r0 = warp * 32 + g;
    const int rows[4] = { r0, r0 + 8, r0 + 16, r0 + 24 };
    const float* sxr[4];
    const uint32_t wbase1 = sbase + W1H_OFF * 4 + lane * 16;
    const uint32_t wbase2 = sbase + W2H_OFF * 4 + lane * 16;
    const uint32_t wbase3 = sbase + W3H_OFF * 4 + lane * 16;
    const int t01 = 2 * tig;

    for (int t = blockIdx.x; t < NTILES; t += NCTA) {
        const int b  = t / (YG * XG);
        const int rm = t % (YG * XG);
        const int py0 = (rm / XG) * TROWS;
        const int px0 = (rm % XG) * TCOLS;

        __syncthreads();   // everyone done with previous sx
        const float* xb = x + (size_t)b * (C_IN * H_IN * W_IN);
        for (int i = tid; i < C_IN * SXH * SXW; i += NTHR) {
            int q = i % SXW;
            int rr = (i / SXW) % SXH;
            int c = i / (SXH * SXW);
            int gxx = px0 + q;
            smem[SX_OFF + i] = (gxx < W_IN) ? xb[(c * H_IN + (py0 + rr)) * W_IN + gxx] : 0.f;
        }
        __syncthreads();

        #pragma unroll
        for (int r = 0; r < 4; r++)
            sxr[r] = smem + SX_OFF + (rows[r] >> 5) * SXW + (rows[r] & 31);

        // ================= layer 1: K=256 (16 ksteps), N=56 (7 j) =========
        float c1[2][7][4];
        #pragma unroll
        for (int j = 0; j < 7; j++) {
            float bv0 = smem[SB1_OFF + j * 8 + t01];
            float bv1 = smem[SB1_OFF + j * 8 + t01 + 1];
            #pragma unroll
            for (int blk = 0; blk < 2; blk++) {
                c1[blk][j][0] = bv0; c1[blk][j][1] = bv1;
                c1[blk][j][2] = bv0; c1[blk][j][3] = bv1;
            }
        }
        #pragma unroll
        for (int ks = 0; ks < 16; ks++) {
            const int k0 = ks * 16;
            int kA0 = ktab[k0 + t01],     kA1 = ktab[k0 + t01 + 1];
            int kB0 = ktab[k0 + t01 + 8], kB1 = ktab[k0 + t01 + 9];
            uint32_t a0 = packh2(sxr[0][kA0], sxr[0][kA1]);
            uint32_t a1 = packh2(sxr[1][kA0], sxr[1][kA1]);
            uint32_t a2 = packh2(sxr[0][kB0], sxr[0][kB1]);
            uint32_t a3 = packh2(sxr[1][kB0], sxr[1][kB1]);
            uint32_t a4 = packh2(sxr[2][kA0], sxr[2][kA1]);
            uint32_t a5 = packh2(sxr[3][kA0], sxr[3][kA1]);
            uint32_t a6 = packh2(sxr[2][kB0], sxr[2][kB1]);
            uint32_t a7 = packh2(sxr[3][kB0], sxr[3][kB1]);
            #pragma unroll
            for (int jp = 0; jp < 4; jp++) {
                uint32_t b0, b1r, b2r, b3r;
                LDS128U(b0, b1r, b2r, b3r, wbase1 + (ks * 4 + jp) * 512);
                MMA16(c1[0][2 * jp], a0, a1, a2, a3, b0, b1r);
                MMA16(c1[1][2 * jp], a4, a5, a6, a7, b0, b1r);
                if (jp < 3) {
                    MMA16(c1[0][2 * jp + 1], a0, a1, a2, a3, b2r, b3r);
                    MMA16(c1[1][2 * jp + 1], a4, a5, a6, a7, b2r, b3r);
                }
            }
        }

        // ---- epilogue 1: relu -> fp16x2 n-pairs -> A2H ----
        #pragma unroll
        for (int blk = 0; blk < 2; blk++) {
            #pragma unroll
            for (int j = 0; j < 7; j++) {
                int n0 = j * 8 + t01;
                int q = j * 4 + tig;
                float vA0 = 0.f, vA1 = 0.f, vB0 = 0.f, vB1 = 0.f;
                if (n0 < 50) {
                    vA0 = fmaxf(c1[blk][j][0], 0.f);
                    vA1 = (n0 + 1 < 50) ? fmaxf(c1[blk][j][1], 0.f) : 0.f;
                    vB0 = fmaxf(c1[blk][j][2], 0.f);
                    vB1 = (n0 + 1 < 50) ? fmaxf(c1[blk][j][3], 0.f) : 0.f;
                }
                su[A2H_OFF + q * A2STR + rows[blk * 2]]     = packh2(vA0, vA1);
                su[A2H_OFF + q * A2STR + rows[blk * 2 + 1]] = packh2(vB0, vB1);
            }
        }
        __syncwarp();

        // ================= layer 2: K=64 (4 ksteps), N=56 =================
        float c2[2][7][4];
        #pragma unroll
        for (int j = 0; j < 7; j++) {
            float bv0 = smem[SB2_OFF + j * 8 + t01];
            float bv1 = smem[SB2_OFF + j * 8 + t01 + 1];
            #pragma unroll
            for (int blk = 0; blk < 2; blk++) {
                c2[blk][j][0] = bv0; c2[blk][j][1] = bv1;
                c2[blk][j][2] = bv0; c2[blk][j][3] = bv1;
            }
        }
        #pragma unroll
        for (int ks = 0; ks < 4; ks++) {
            int qb = 8 * ks + tig;
            uint32_t a0 = su[A2H_OFF + qb * A2STR + rows[0]];
            uint32_t a1 = su[A2H_OFF + qb * A2STR + rows[1]];
            uint32_t a2 = su[A2H_OFF + (qb + 4) * A2STR + rows[0]];
            uint32_t a3 = su[A2H_OFF + (qb + 4) * A2STR + rows[1]];
            uint32_t a4 = su[A2H_OFF + qb * A2STR + rows[2]];
            uint32_t a5 = su[A2H_OFF + qb * A2STR + rows[3]];
            uint32_t a6 = su[A2H_OFF + (qb + 4) * A2STR + rows[2]];
            uint32_t a7 = su[A2H_OFF + (qb + 4) * A2STR + rows[3]];
            #pragma unroll
            for (int jp = 0; jp < 4; jp++) {
                uint32_t b0, b1r, b2r, b3r;
                LDS128U(b0, b1r, b2r, b3r, wbase2 + (ks * 4 + jp) * 512);
                MMA16(c2[0][2 * jp], a0, a1, a2, a3, b0, b1r);
                MMA16(c2[1][2 * jp], a4, a5, a6, a7, b0, b1r);
                if (jp < 3) {
                    MMA16(c2[0][2 * jp + 1], a0, a1, a2, a3, b2r, b3r);
                    MMA16(c2[1][2 * jp + 1], a4, a5, a6, a7, b2r, b3r);
                }
            }
        }
        __syncwarp();

        // ---- epilogue 2: h2 -> A2H ----
        #pragma unroll
        for (int blk = 0; blk < 2; blk++) {
            #pragma unroll
            for (int j = 0; j < 7; j++) {
                int n0 = j * 8 + t01;
                int q = j * 4 + tig;
                float vA0 = 0.f, vA1 = 0.f, vB0 = 0.f, vB1 = 0.f;
                if (n0 < 50) {
                    vA0 = fmaxf(c2[blk][j][0], 0.f);
                    vA1 = (n0 + 1 < 50) ? fmaxf(c2[blk][j][1], 0.f) : 0.f;
                    vB0 = fmaxf(c2[blk][j][2], 0.f);
                    vB1 = (n0 + 1 < 50) ? fmaxf(c2[blk][j][3], 0.f) : 0.f;
                }
                su[A2H_OFF + q * A2STR + rows[blk * 2]]     = packh2(vA0, vA1);
                su[A2H_OFF + q * A2STR + rows[blk * 2 + 1]] = packh2(vB0, vB1);
            }
        }
        __syncwarp();

        // ================= layer 3: K=64, N=16 =================
        float c3[2][2][4];
        #pragma unroll
        for (int j = 0; j < 2; j++) {
            float bv0 = smem[SB3_OFF + j * 8 + t01];
            float bv1 = smem[SB3_OFF + j * 8 + t01 + 1];
            #pragma unroll
            for (int blk = 0; blk < 2; blk++) {
                c3[blk][j][0] = bv0; c3[blk][j][1] = bv1;
                c3[blk][j][2] = bv0; c3[blk][j][3] = bv1;
            }
        }
        #pragma unroll
        for (int ks = 0; ks < 4; ks++) {
            int qb = 8 * ks + tig;
            uint32_t a0 = su[A2H_OFF + qb * A2STR + rows[0]];
            uint32_t a1 = su[A2H_OFF + qb * A2STR + rows[1]];
            uint32_t a2 = su[A2H_OFF + (qb + 4) * A2STR + rows[0]];
            uint32_t a3 = su[A2H_OFF + (qb + 4) * A2STR + rows[1]];
            uint32_t a4 = su[A2H_OFF + qb * A2STR + rows[2]];
            uint32_t a5 = su[A2H_OFF + qb * A2STR + rows[3]];
            uint32_t a6 = su[A2H_OFF + (qb + 4) * A2STR + rows[2]];
            uint32_t a7 = su[A2H_OFF + (qb + 4) * A2STR + rows[3]];
            uint32_t b0, b1r, b2r, b3r;
            LDS128U(b0, b1r, b2r, b3r, wbase3 + ks * 512);
            MMA16(c3[0][0], a0, a1, a2, a3, b0,  b1r);
            MMA16(c3[1][0], a4, a5, a6, a7, b0,  b1r);
            MMA16(c3[0][1], a0, a1, a2, a3, b2r, b3r);
            MMA16(c3[1][1], a4, a5, a6, a7, b2r, b3r);
        }

        // ---- epilogue 3: y -> g_y ----
        #pragma unroll
        for (int blk = 0; blk < 2; blk++) {
            #pragma unroll
            for (int j = 0; j < 2; j++) {
                #pragma unroll
                for (int d = 0; d < 4; d++) {
                    int n = j * 8 + t01 + (d & 1);
                    if (n < 9) {
                        int row = rows[blk * 2 + ((d >= 2) ? 1 : 0)];
                        int py = py0 + (row >> 5);
                        int px = px0 + (row & 31);
                        if (px < HP)
                            g_y[(((size_t)n * B2 + b) * HP + py) * HP + px] = c3[blk][j][d];
                    }
                }
            }
        }
    }
}

// ---- fold (overlap-add + divisor) as pure gather ----
__global__ __launch_bounds__(256) void fold_kernel(float* __restrict__ out)
{
    int idx = blockIdx.x * blockDim.x + threadIdx.x;
    const int total = B2 * OUT_H * OUT_H;
    if (idx >= total) return;
    int oj = idx % OUT_H;
    int t  = idx / OUT_H;
    int oi = t % OUT_H;
    int b  = t / OUT_H;

    float acc = 0.f;
    int cnt = 0;
    #pragma unroll
    for (int di = 0; di < KO; di++) {
        int pi = oi - di;
        if (pi < 0 || pi >= HP) continue;
        #pragma unroll
        for (int dj = 0; dj < KO; dj++) {
            int pj = oj - dj;
            if (pj < 0 || pj >= HP) continue;
            acc += g_y[((di * KO + dj) * B2 + b) * (HP * HP) + pi * HP + pj];
            cnt++;
        }
    }
    out[idx] = acc / (float)cnt;
}

extern "C" void kernel_launch(void* const* d_in, const int* in_sizes, int n_in,
                              void* d_out, int out_size)
{
    const float* x  = (const float*)d_in[0];
    const float* W1 = (const float*)d_in[1];
    const float* b1 = (const float*)d_in[2];
    const float* W2 = (const float*)d_in[3];
    const float* b2 = (const float*)d_in[4];
    const float* W3 = (const float*)d_in[5];
    const float* b3 = (const float*)d_in[6];
    float* out = (float*)d_out;

    const int smem_bytes = SMEM_WORDS * 4;   // 86,080 B
    cudaFuncSetAttribute(mlp_kernel,
                         cudaFuncAttributeMaxDynamicSharedMemorySize, smem_bytes);

    mlp_kernel<<<NCTA, NTHR, smem_bytes>>>(x, W1, b1, W2, b2, W3, b3);

    const int total = B2 * OUT_H * OUT_H;
    fold_kernel<<<(total + 255) / 256, 256>>>(out);
}